// round 5
// baseline (speedup 1.0000x reference)
#include <cuda_runtime.h>
#include <cstdint>

#define NNODES 50000
#define FEDGE  128
#define HDIM   256
#define APAD   34      // k-major A tile row pitch (floats): keeps LDS.64 aligned

// ---------------- scratch (no allocations allowed) ----------------
static __device__ float g_mean[NNODES * FEDGE];   // raw sums (mean folded later)
static __device__ float g_cnt[NNODES];
static __device__ float g_node1[NNODES * HDIM];
static __device__ float g_node2[NNODES * HDIM];
static __device__ float g_ps[NNODES];
static __device__ float g_pd[NNODES];

__device__ __forceinline__ int clamp_idx(int v) {
    v = v < 0 ? 0 : v;
    return v >= NNODES ? NNODES - 1 : v;
}

// ---------------- kernel 0: zero the accumulators ----------------
__global__ void zero_kernel() {
    int i = blockIdx.x * blockDim.x + threadIdx.x;
    const int total4 = (NNODES * FEDGE) / 4;
    if (i < total4)
        reinterpret_cast<float4*>(g_mean)[i] = make_float4(0.f, 0.f, 0.f, 0.f);
    if (i < NNODES) g_cnt[i] = 0.f;
}

// ---------------- kernel 1: scatter-add (vector atomics) ----------------
__global__ void scatter_kernel(const float* __restrict__ edge_attr,
                               const int* __restrict__ edge_index,
                               int E) {
    int gt = blockIdx.x * blockDim.x + threadIdx.x;
    int e = gt >> 5;
    int lane = gt & 31;
    if (e >= E) return;
    int src = clamp_idx(edge_index[e]);
    float4 v = reinterpret_cast<const float4*>(edge_attr + (size_t)e * FEDGE)[lane];
    float* dst = g_mean + (size_t)src * FEDGE + lane * 4;
    asm volatile("red.global.add.v4.f32 [%0], {%1,%2,%3,%4};"
                 :: "l"(dst), "f"(v.x), "f"(v.y), "f"(v.z), "f"(v.w) : "memory");
    if (lane == 0) atomicAdd(g_cnt + src, 1.0f);
}

// ---------------- kernel 2: fused GEMM + bias + sigmoid (FFMA2) ------------
// C[M,256] = sigmoid([A1 | A2/cnt] @ W + b). Mean division folded into load.
// A tile stored k-major: As[k*APAD + r], r = row 0..31. Row-pair (2i,2i+1) at
// column k is one aligned broadcast LDS.64 -> packed f32x2 operand.
// Block 256 thr; thread (g = tid>>6, c = tid&63) owns rows g*8..g*8+7 (as 4
// pairs) x cols c*4..c*4+3. acc[i][j] = f32x2 (C[2i][j], C[2i+1][j]).
// Per k: 4 LDS.64 + 1 LDG.128 + 4 MOV.b64 + 16 FFMA2 (= 32 FMA).
template <int K>
__global__ __launch_bounds__(256) void gemm_sigmoid_kernel(
        const float* __restrict__ A1, int K1,
        const float* __restrict__ A2,
        const float* __restrict__ W,
        const float* __restrict__ b,
        float* __restrict__ out, int M) {
    extern __shared__ float As[];                   // K * APAD floats
    const int tid = threadIdx.x;
    const int row0 = blockIdx.x * 32;
    const int g = tid >> 6;
    const int c = tid & 63;
    const int K4 = K / 4;

    // Tile load: lane r gathers row (row0+r) float4 at k4, writes transposed.
    // Lanes within a warp vary r -> STS banks (2k+r)%32 consecutive: conflict-free.
    {
        const int K14 = K1 / 4;
        const float4* A14 = reinterpret_cast<const float4*>(A1);
        const float4* A24 = reinterpret_cast<const float4*>(A2);
        for (int idx = tid; idx < 32 * K4; idx += 256) {
            int k4 = idx >> 5;
            int r = idx & 31;
            int row = row0 + r;
            float4 v = make_float4(0.f, 0.f, 0.f, 0.f);
            if (row < M) {
                if (k4 < K14) {
                    v = A14[(size_t)row * K14 + k4];
                } else {
                    v = A24[(size_t)row * (FEDGE / 4) + (k4 - K14)];
                    float inv = 1.0f / fmaxf(g_cnt[row], 1.0f);
                    v.x *= inv; v.y *= inv; v.z *= inv; v.w *= inv;
                }
            }
            int k = k4 * 4;
            As[(k + 0) * APAD + r] = v.x;
            As[(k + 1) * APAD + r] = v.y;
            As[(k + 2) * APAD + r] = v.z;
            As[(k + 3) * APAD + r] = v.w;
        }
    }
    __syncthreads();

    unsigned long long acc[4][4];
#pragma unroll
    for (int i = 0; i < 4; i++)
#pragma unroll
        for (int j = 0; j < 4; j++) acc[i][j] = 0ULL;

    const float4* W4 = reinterpret_cast<const float4*>(W);

#pragma unroll 2
    for (int k = 0; k < K; k++) {
        float4 w = W4[(size_t)k * 64 + c];          // L2-hot
        unsigned long long wp[4];
        asm("mov.b64 %0,{%1,%1};" : "=l"(wp[0]) : "f"(w.x));
        asm("mov.b64 %0,{%1,%1};" : "=l"(wp[1]) : "f"(w.y));
        asm("mov.b64 %0,{%1,%1};" : "=l"(wp[2]) : "f"(w.z));
        asm("mov.b64 %0,{%1,%1};" : "=l"(wp[3]) : "f"(w.w));
        const unsigned long long* Ap =
            reinterpret_cast<const unsigned long long*>(As + k * APAD + g * 8);
        unsigned long long ap[4];
#pragma unroll
        for (int i = 0; i < 4; i++) ap[i] = Ap[i];  // broadcast LDS.64
#pragma unroll
        for (int i = 0; i < 4; i++)
#pragma unroll
            for (int j = 0; j < 4; j++)
                asm("fma.rn.f32x2 %0,%1,%2,%3;"
                    : "=l"(acc[i][j]) : "l"(ap[i]), "l"(wp[j]), "l"(acc[i][j]));
    }

    float4 bv = reinterpret_cast<const float4*>(b)[c];
    float bvj[4] = {bv.x, bv.y, bv.z, bv.w};
#pragma unroll
    for (int i = 0; i < 4; i++) {
        int row = row0 + g * 8 + 2 * i;
        float lo[4], hi[4];
#pragma unroll
        for (int j = 0; j < 4; j++) {
            asm("mov.b64 {%0,%1},%2;" : "=f"(lo[j]), "=f"(hi[j]) : "l"(acc[i][j]));
            lo[j] = 1.0f / (1.0f + __expf(-(lo[j] + bvj[j])));
            hi[j] = 1.0f / (1.0f + __expf(-(hi[j] + bvj[j])));
        }
        if (row < M)
            reinterpret_cast<float4*>(out + (size_t)row * HDIM)[c] =
                make_float4(lo[0], lo[1], lo[2], lo[3]);
        if (row + 1 < M)
            reinterpret_cast<float4*>(out + (size_t)(row + 1) * HDIM)[c] =
                make_float4(hi[0], hi[1], hi[2], hi[3]);
    }
}

// ---------------- kernel 3: per-node partial dot products -------------------
__global__ void pspd_kernel(const float* __restrict__ wf, int Nn) {
    int gt = blockIdx.x * blockDim.x + threadIdx.x;
    int n = gt >> 5;
    int lane = gt & 31;
    if (n >= Nn) return;
    const float4* row = reinterpret_cast<const float4*>(g_node2 + (size_t)n * HDIM);
    const float4* wfs = reinterpret_cast<const float4*>(wf);
    const float4* wfd = reinterpret_cast<const float4*>(wf + HDIM);
    float s = 0.f, d = 0.f;
#pragma unroll
    for (int k = lane; k < HDIM / 4; k += 32) {
        float4 v = row[k];
        float4 a = wfs[k];
        float4 bq = wfd[k];
        s += v.x * a.x + v.y * a.y + v.z * a.z + v.w * a.w;
        d += v.x * bq.x + v.y * bq.y + v.z * bq.z + v.w * bq.w;
    }
#pragma unroll
    for (int o = 16; o; o >>= 1) {
        s += __shfl_xor_sync(0xFFFFFFFFu, s, o);
        d += __shfl_xor_sync(0xFFFFFFFFu, d, o);
    }
    if (lane == 0) { g_ps[n] = s; g_pd[n] = d; }
}

// ---------------- kernel 4: edge embeddings + logits ----------------
__global__ void edge_kernel(const int* __restrict__ edge_index,
                            const float* __restrict__ bf,
                            float* __restrict__ out, int E) {
    int gt = blockIdx.x * blockDim.x + threadIdx.x;
    int e = gt >> 5;
    int lane = gt & 31;
    if (e >= E) return;
    int s = clamp_idx(edge_index[e]);
    int d = clamp_idx(edge_index[E + e]);
    const float4* rs = reinterpret_cast<const float4*>(g_node2 + (size_t)s * HDIM);
    const float4* rd = reinterpret_cast<const float4*>(g_node2 + (size_t)d * HDIM);
    float4* o4 = reinterpret_cast<float4*>(out + (size_t)E + (size_t)e * (2 * HDIM));
    __stcs(o4 + lane,      rs[lane]);
    __stcs(o4 + 32 + lane, rs[32 + lane]);
    __stcs(o4 + 64 + lane, rd[lane]);
    __stcs(o4 + 96 + lane, rd[32 + lane]);
    if (lane == 0) __stcs(out + e, g_ps[s] + g_pd[d] + bf[0]);
}

// ---------------- launch ----------------
extern "C" void kernel_launch(void* const* d_in, const int* in_sizes, int n_in,
                              void* d_out, int out_size) {
    const float* edge_attr  = (const float*)d_in[0];
    const int*   edge_index = (const int*)d_in[1];
    const float* node_attr  = (const float*)d_in[2];
    const float* w0 = (const float*)d_in[3];
    const float* b0 = (const float*)d_in[4];
    const float* w1 = (const float*)d_in[5];
    const float* b1 = (const float*)d_in[6];
    const float* wf = (const float*)d_in[7];
    const float* bf = (const float*)d_in[8];
    float* out = (float*)d_out;

    const int E  = in_sizes[1] / 2;
    const int Nn = in_sizes[2] / FEDGE;

    float *mean_p, *node1_p, *node2_p;
    cudaGetSymbolAddress((void**)&mean_p,  g_mean);
    cudaGetSymbolAddress((void**)&node1_p, g_node1);
    cudaGetSymbolAddress((void**)&node2_p, g_node2);

    const int smem256 = 256 * APAD * sizeof(float);   // 34816 B
    const int smem384 = 384 * APAD * sizeof(float);   // 52224 B (>48KB opt-in)
    cudaFuncSetAttribute(gemm_sigmoid_kernel<256>,
                         cudaFuncAttributeMaxDynamicSharedMemorySize, smem256);
    cudaFuncSetAttribute(gemm_sigmoid_kernel<384>,
                         cudaFuncAttributeMaxDynamicSharedMemorySize, smem384);

    {
        int total4 = (NNODES * FEDGE) / 4;
        zero_kernel<<<(total4 + 255) / 256, 256>>>();
    }
    {
        long long threads = (long long)E * 32;
        scatter_kernel<<<(int)((threads + 255) / 256), 256>>>(edge_attr, edge_index, E);
    }

    gemm_sigmoid_kernel<256><<<(Nn + 31) / 32, 256, smem256>>>(
        node_attr, FEDGE, mean_p, w0, b0, node1_p, Nn);
    gemm_sigmoid_kernel<384><<<(Nn + 31) / 32, 256, smem384>>>(
        node1_p, HDIM, mean_p, w1, b1, node2_p, Nn);
    {
        long long threads = (long long)Nn * 32;
        pspd_kernel<<<(int)((threads + 255) / 256), 256>>>(wf, Nn);
    }
    {
        long long threads = (long long)E * 32;
        edge_kernel<<<(int)((threads + 255) / 256), 256>>>(edge_index, bf, out, E);
    }
}

// round 8
// speedup vs baseline: 1.5600x; 1.5600x over previous
#include <cuda_runtime.h>
#include <cstdint>

#define NNODES 50000
#define FEDGE  128
#define HDIM   256

// ---------------- scratch (no allocations allowed) ----------------
static __device__ float g_mean[NNODES * FEDGE];    // raw sums
static __device__ float g_cnt[NNODES];
static __device__ float g_node1[NNODES * HDIM];
static __device__ float g_node2[NNODES * HDIM];
static __device__ float g_ps[NNODES];
static __device__ float g_pd[NNODES];
static __device__ unsigned g_w0t[HDIM * 256];      // Wt[n][k], tf32 bits
static __device__ unsigned g_w1t[HDIM * 384];

__device__ __forceinline__ int clamp_idx(int v) {
    v = v < 0 ? 0 : v;
    return v >= NNODES ? NNODES - 1 : v;
}
__device__ __forceinline__ unsigned f2tf32(float x) {
    unsigned u;
    asm("cvt.rn.tf32.f32 %0, %1;" : "=r"(u) : "f"(x));
    return u;
}

// ---------------- kernel 0: zero ----------------
__global__ void zero_kernel() {
    int i = blockIdx.x * blockDim.x + threadIdx.x;
    const int total4 = (NNODES * FEDGE) / 4;
    if (i < total4)
        reinterpret_cast<float4*>(g_mean)[i] = make_float4(0.f, 0.f, 0.f, 0.f);
    if (i < NNODES) g_cnt[i] = 0.f;
}

// ---------------- kernel 1: scatter-add ----------------
__global__ void scatter_kernel(const float* __restrict__ edge_attr,
                               const int* __restrict__ edge_index, int E) {
    int gt = blockIdx.x * blockDim.x + threadIdx.x;
    int e = gt >> 5, lane = gt & 31;
    if (e >= E) return;
    int src = clamp_idx(edge_index[e]);
    float4 v = reinterpret_cast<const float4*>(edge_attr + (size_t)e * FEDGE)[lane];
    float* dst = g_mean + (size_t)src * FEDGE + lane * 4;
    asm volatile("red.global.add.v4.f32 [%0], {%1,%2,%3,%4};"
                 :: "l"(dst), "f"(v.x), "f"(v.y), "f"(v.z), "f"(v.w) : "memory");
    if (lane == 0) atomicAdd(g_cnt + src, 1.0f);
}

// ---------------- kernel 1b: transpose W -> Wt[n][k] (tf32 bits) ----------
__global__ void transpose_kernel(const float* __restrict__ W,
                                 unsigned* __restrict__ Wt, int K) {
    int i = blockIdx.x * blockDim.x + threadIdx.x;
    if (i >= 256 * K) return;
    int n = i / K, k = i - n * K;
    Wt[i] = f2tf32(W[(size_t)k * 256 + n]);
}

// ---------------- kernel 2: tf32 mma.sync GEMM + bias + sigmoid ------------
// C[M,256] = sigmoid([A1 | A2/cnt] @ W + b).
// Block 256 thr = 8 warps (2M x 4N). Block tile 128x128 (grid.y=2 covers N=256).
// Warp tile 64x32 = 4x4 m16n8 mma tiles; K chunked by 32 via smem.
// smem pitch 36 floats -> frag LDS banks (4g+t) all distinct (conflict-free).
#define PITCH 36
template <int K>
__global__ __launch_bounds__(256) void gemm_tc_kernel(
        const float* __restrict__ A1, int K1,
        const float* __restrict__ A2,
        const unsigned* __restrict__ Wt,   // [256, K] tf32 bits
        const float* __restrict__ b,
        float* __restrict__ out, int M) {
    __shared__ unsigned As[128 * PITCH];
    __shared__ unsigned Bs[128 * PITCH];
    const int tid = threadIdx.x;
    const int warp = tid >> 5, lane = tid & 31;
    const int g = lane >> 2, t = lane & 3;
    const int warp_m = warp & 1, warp_n = warp >> 1;
    const int row0 = blockIdx.x * 128;
    const int col0 = blockIdx.y * 128;
    const int K14 = K1 / 4;
    const int NCH = K / 32;

    float c[4][4][4];
#pragma unroll
    for (int i = 0; i < 4; i++)
#pragma unroll
        for (int j = 0; j < 4; j++)
#pragma unroll
            for (int q = 0; q < 4; q++) c[i][j][q] = 0.f;

    for (int ch = 0; ch < NCH; ch++) {
        // ---- stage A chunk [128 rows x 32 k] (tf32-convert, fold mean) ----
#pragma unroll
        for (int rep = 0; rep < 4; rep++) {
            int idx = tid + rep * 256;               // 0..1023
            int r = idx >> 3, c4 = idx & 7;
            int row = row0 + r;
            int k4 = ch * 8 + c4;
            float4 v = make_float4(0.f, 0.f, 0.f, 0.f);
            if (row < M) {
                if (k4 < K14) {
                    v = reinterpret_cast<const float4*>(A1)[(size_t)row * K14 + k4];
                } else {
                    v = reinterpret_cast<const float4*>(A2)[(size_t)row * 32 + (k4 - K14)];
                    float inv = 1.0f / fmaxf(g_cnt[row], 1.0f);
                    v.x *= inv; v.y *= inv; v.z *= inv; v.w *= inv;
                }
            }
            unsigned* p = As + r * PITCH + c4 * 4;
            p[0] = f2tf32(v.x); p[1] = f2tf32(v.y);
            p[2] = f2tf32(v.z); p[3] = f2tf32(v.w);
        }
        // ---- stage B chunk [128 n x 32 k] from Wt (already tf32) ----
#pragma unroll
        for (int rep = 0; rep < 4; rep++) {
            int idx = tid + rep * 256;
            int n = idx >> 3, c4 = idx & 7;
            uint4 v = reinterpret_cast<const uint4*>(Wt)
                        [(size_t)(col0 + n) * (K / 4) + ch * 8 + c4];
            unsigned* p = Bs + n * PITCH + c4 * 4;
            p[0] = v.x; p[1] = v.y; p[2] = v.z; p[3] = v.w;
        }
        __syncthreads();

        // ---- 4 k-steps of k8 ----
#pragma unroll
        for (int kk = 0; kk < 32; kk += 8) {
            unsigned a[4][4], bb[4][2];
#pragma unroll
            for (int mt = 0; mt < 4; mt++) {
                int r = warp_m * 64 + mt * 16 + g;
                a[mt][0] = As[r * PITCH + kk + t];
                a[mt][1] = As[(r + 8) * PITCH + kk + t];
                a[mt][2] = As[r * PITCH + kk + t + 4];
                a[mt][3] = As[(r + 8) * PITCH + kk + t + 4];
            }
#pragma unroll
            for (int nt = 0; nt < 4; nt++) {
                int n = warp_n * 32 + nt * 8 + g;
                bb[nt][0] = Bs[n * PITCH + kk + t];
                bb[nt][1] = Bs[n * PITCH + kk + t + 4];
            }
#pragma unroll
            for (int mt = 0; mt < 4; mt++)
#pragma unroll
                for (int nt = 0; nt < 4; nt++)
                    asm volatile(
                        "mma.sync.aligned.m16n8k8.row.col.f32.tf32.tf32.f32 "
                        "{%0,%1,%2,%3}, {%4,%5,%6,%7}, {%8,%9}, {%0,%1,%2,%3};"
                        : "+f"(c[mt][nt][0]), "+f"(c[mt][nt][1]),
                          "+f"(c[mt][nt][2]), "+f"(c[mt][nt][3])
                        : "r"(a[mt][0]), "r"(a[mt][1]), "r"(a[mt][2]), "r"(a[mt][3]),
                          "r"(bb[nt][0]), "r"(bb[nt][1]));
        }
        __syncthreads();
    }

    // ---- epilogue: bias + sigmoid, float2 stores ----
#pragma unroll
    for (int mt = 0; mt < 4; mt++) {
        int r0 = row0 + warp_m * 64 + mt * 16 + g;
#pragma unroll
        for (int nt = 0; nt < 4; nt++) {
            int col = col0 + warp_n * 32 + nt * 8 + 2 * t;
            float b0v = b[col], b1v = b[col + 1];
            if (r0 < M) {
                float2 o;
                o.x = 1.0f / (1.0f + __expf(-(c[mt][nt][0] + b0v)));
                o.y = 1.0f / (1.0f + __expf(-(c[mt][nt][1] + b1v)));
                *reinterpret_cast<float2*>(out + (size_t)r0 * HDIM + col) = o;
            }
            if (r0 + 8 < M) {
                float2 o;
                o.x = 1.0f / (1.0f + __expf(-(c[mt][nt][2] + b0v)));
                o.y = 1.0f / (1.0f + __expf(-(c[mt][nt][3] + b1v)));
                *reinterpret_cast<float2*>(out + (size_t)(r0 + 8) * HDIM + col) = o;
            }
        }
    }
}

// ---------------- kernel 3: per-node partial dot products ----------------
__global__ void pspd_kernel(const float* __restrict__ wf, int Nn) {
    int gt = blockIdx.x * blockDim.x + threadIdx.x;
    int n = gt >> 5, lane = gt & 31;
    if (n >= Nn) return;
    const float4* row = reinterpret_cast<const float4*>(g_node2 + (size_t)n * HDIM);
    const float4* wfs = reinterpret_cast<const float4*>(wf);
    const float4* wfd = reinterpret_cast<const float4*>(wf + HDIM);
    float s = 0.f, d = 0.f;
#pragma unroll
    for (int k = lane; k < HDIM / 4; k += 32) {
        float4 v = row[k], a = wfs[k], bq = wfd[k];
        s += v.x * a.x + v.y * a.y + v.z * a.z + v.w * a.w;
        d += v.x * bq.x + v.y * bq.y + v.z * bq.z + v.w * bq.w;
    }
#pragma unroll
    for (int o = 16; o; o >>= 1) {
        s += __shfl_xor_sync(0xFFFFFFFFu, s, o);
        d += __shfl_xor_sync(0xFFFFFFFFu, d, o);
    }
    if (lane == 0) { g_ps[n] = s; g_pd[n] = d; }
}

// ---------------- kernel 4: edge embeddings + logits ----------------
__global__ void edge_kernel(const int* __restrict__ edge_index,
                            const float* __restrict__ bf,
                            float* __restrict__ out, int E) {
    int gt = blockIdx.x * blockDim.x + threadIdx.x;
    int e = gt >> 5, lane = gt & 31;
    if (e >= E) return;
    int s = clamp_idx(edge_index[e]);
    int d = clamp_idx(edge_index[E + e]);
    const float4* rs = reinterpret_cast<const float4*>(g_node2 + (size_t)s * HDIM);
    const float4* rd = reinterpret_cast<const float4*>(g_node2 + (size_t)d * HDIM);
    float4* o4 = reinterpret_cast<float4*>(out + (size_t)E + (size_t)e * (2 * HDIM));
    __stcs(o4 + lane,      rs[lane]);
    __stcs(o4 + 32 + lane, rs[32 + lane]);
    __stcs(o4 + 64 + lane, rd[lane]);
    __stcs(o4 + 96 + lane, rd[32 + lane]);
    if (lane == 0) __stcs(out + e, g_ps[s] + g_pd[d] + bf[0]);
}

// ---------------- launch ----------------
extern "C" void kernel_launch(void* const* d_in, const int* in_sizes, int n_in,
                              void* d_out, int out_size) {
    const float* edge_attr  = (const float*)d_in[0];
    const int*   edge_index = (const int*)d_in[1];
    const float* node_attr  = (const float*)d_in[2];
    const float* w0 = (const float*)d_in[3];
    const float* b0 = (const float*)d_in[4];
    const float* w1 = (const float*)d_in[5];
    const float* b1 = (const float*)d_in[6];
    const float* wf = (const float*)d_in[7];
    const float* bf = (const float*)d_in[8];
    float* out = (float*)d_out;

    const int E  = in_sizes[1] / 2;
    const int Nn = in_sizes[2] / FEDGE;

    float *mean_p, *node1_p, *node2_p;
    unsigned *w0t_p, *w1t_p;
    cudaGetSymbolAddress((void**)&mean_p,  g_mean);
    cudaGetSymbolAddress((void**)&node1_p, g_node1);
    cudaGetSymbolAddress((void**)&node2_p, g_node2);
    cudaGetSymbolAddress((void**)&w0t_p,   g_w0t);
    cudaGetSymbolAddress((void**)&w1t_p,   g_w1t);

    {
        int total4 = (NNODES * FEDGE) / 4;
        zero_kernel<<<(total4 + 255) / 256, 256>>>();
    }
    {
        long long threads = (long long)E * 32;
        scatter_kernel<<<(int)((threads + 255) / 256), 256>>>(edge_attr, edge_index, E);
    }
    transpose_kernel<<<(256 * 256 + 255) / 256, 256>>>(w0, w0t_p, 256);
    transpose_kernel<<<(256 * 384 + 255) / 256, 256>>>(w1, w1t_p, 384);

    dim3 grid((Nn + 127) / 128, 2);
    gemm_tc_kernel<256><<<grid, 256>>>(node_attr, FEDGE, mean_p, w0t_p, b0, node1_p, Nn);
    gemm_tc_kernel<384><<<grid, 256>>>(node1_p, HDIM, mean_p, w1t_p, b1, node2_p, Nn);
    {
        long long threads = (long long)Nn * 32;
        pspd_kernel<<<(int)((threads + 255) / 256), 256>>>(wf, Nn);
    }
    {
        long long threads = (long long)E * 32;
        edge_kernel<<<(int)((threads + 255) / 256), 256>>>(edge_index, bf, out, E);
    }
}

// round 9
// speedup vs baseline: 1.7276x; 1.1074x over previous
#include <cuda_runtime.h>
#include <cstdint>

#define NNODES 50000
#define FEDGE  128
#define HDIM   256

// ---------------- scratch (no allocations allowed) ----------------
static __device__ float    g_mean[NNODES * FEDGE];   // fp32 sums -> tf32 bits after mean_fin
static __device__ float    g_cnt[NNODES];
static __device__ unsigned g_a0[NNODES * FEDGE];     // node_attr as tf32 bits
static __device__ float    g_node1[NNODES * HDIM];   // tf32 bits (layer0 out, layer1 in)
static __device__ float    g_node2[NNODES * HDIM];   // fp32
static __device__ float    g_ps[NNODES];
static __device__ float    g_pd[NNODES];
static __device__ unsigned g_w0t[HDIM * 256];        // Wt[n][k] tf32 bits
static __device__ unsigned g_w1t[HDIM * 384];

__device__ __forceinline__ int clamp_idx(int v) {
    v = v < 0 ? 0 : v;
    return v >= NNODES ? NNODES - 1 : v;
}
__device__ __forceinline__ unsigned f2tf32(float x) {
    unsigned u;
    asm("cvt.rn.tf32.f32 %0, %1;" : "=r"(u) : "f"(x));
    return u;
}
__device__ __forceinline__ uint32_t smem_u32(const void* p) {
    uint32_t a;
    asm("{ .reg .u64 t; cvta.to.shared.u64 t, %1; cvt.u32.u64 %0, t; }" : "=r"(a) : "l"(p));
    return a;
}

// ---------------- kernel 0: zero ----------------
__global__ void zero_kernel() {
    int i = blockIdx.x * blockDim.x + threadIdx.x;
    const int total4 = (NNODES * FEDGE) / 4;
    if (i < total4)
        reinterpret_cast<float4*>(g_mean)[i] = make_float4(0.f, 0.f, 0.f, 0.f);
    if (i < NNODES) g_cnt[i] = 0.f;
}

// ---------------- kernel 1: scatter-add ----------------
__global__ void scatter_kernel(const float* __restrict__ edge_attr,
                               const int* __restrict__ edge_index, int E) {
    int gt = blockIdx.x * blockDim.x + threadIdx.x;
    int e = gt >> 5, lane = gt & 31;
    if (e >= E) return;
    int src = clamp_idx(edge_index[e]);
    float4 v = reinterpret_cast<const float4*>(edge_attr + (size_t)e * FEDGE)[lane];
    float* dst = g_mean + (size_t)src * FEDGE + lane * 4;
    asm volatile("red.global.add.v4.f32 [%0], {%1,%2,%3,%4};"
                 :: "l"(dst), "f"(v.x), "f"(v.y), "f"(v.z), "f"(v.w) : "memory");
    if (lane == 0) atomicAdd(g_cnt + src, 1.0f);
}

// ---------------- kernel 1b: transpose W -> Wt[n][k] (tf32 bits) ----------
__global__ void transpose_kernel(const float* __restrict__ W,
                                 unsigned* __restrict__ Wt, int K) {
    int i = blockIdx.x * blockDim.x + threadIdx.x;
    if (i >= 256 * K) return;
    int n = i / K, k = i - n * K;
    Wt[i] = f2tf32(W[(size_t)k * 256 + n]);
}

// ---------------- kernel 1c: node_attr -> tf32 bits ----------------
__global__ void a0_convert_kernel(const float* __restrict__ na, int n4) {
    int i = blockIdx.x * blockDim.x + threadIdx.x;
    if (i >= n4) return;
    float4 v = reinterpret_cast<const float4*>(na)[i];
    reinterpret_cast<uint4*>(g_a0)[i] =
        make_uint4(f2tf32(v.x), f2tf32(v.y), f2tf32(v.z), f2tf32(v.w));
}

// ---------------- kernel 1d: mean = sum/cnt, rewrite as tf32 bits ----------
__global__ void mean_fin_kernel() {
    int i = blockIdx.x * blockDim.x + threadIdx.x;
    const int total4 = NNODES * FEDGE / 4;
    if (i >= total4) return;
    float inv = 1.0f / fmaxf(g_cnt[i >> 5], 1.0f);
    float4 v = reinterpret_cast<float4*>(g_mean)[i];
    reinterpret_cast<uint4*>(g_mean)[i] =
        make_uint4(f2tf32(v.x * inv), f2tf32(v.y * inv),
                   f2tf32(v.z * inv), f2tf32(v.w * inv));
}

// ---------------- kernel 2: tf32 mma.sync GEMM, cp.async double-buffered ---
// C[M,256] = sigmoid([A1 | A2] @ W + b); A1/A2/Wt are pre-converted tf32 bits.
// Block 256 thr = 8 warps (2M x 4N); block tile 128x128 (grid.y=2); warp tile
// 64x32; K chunked by 32. 2-stage cp.async pipeline overlaps loads with HMMA.
#define PITCH 36
#define BUFW  (128 * PITCH)          // words per buffer
template <int K, bool CVT>
__global__ __launch_bounds__(256) void gemm_tc_kernel(
        const unsigned* __restrict__ A1, int K1,
        const unsigned* __restrict__ A2,
        const unsigned* __restrict__ Wt,
        const float* __restrict__ b,
        float* __restrict__ out, int M) {
    extern __shared__ unsigned smem_u[];              // 4 * BUFW words = 73728 B
    const uint32_t sbase = smem_u32(smem_u);
    const int tid = threadIdx.x;
    const int warp = tid >> 5, lane = tid & 31;
    const int g = lane >> 2, t = lane & 3;
    const int warp_m = warp & 1, warp_n = warp >> 1;
    const int row0 = blockIdx.x * 128;
    const int col0 = blockIdx.y * 128;
    const int K14 = K1 / 4;
    const int NCH = K / 32;

    auto stage = [&](int ch, int buf) {
#pragma unroll
        for (int rep = 0; rep < 4; rep++) {
            int idx = tid + rep * 256;                // 0..1023
            int r = idx >> 3, c4 = idx & 7;
            {   // A: 16B per transfer, zero-fill OOB rows
                int k4 = ch * 8 + c4;
                int row = row0 + r;
                int rowc = row < M ? row : M - 1;
                const unsigned* gsrc = (k4 < K14)
                    ? A1 + (size_t)rowc * K1 + k4 * 4
                    : A2 + (size_t)rowc * FEDGE + (k4 - K14) * 4;
                unsigned ss = (row < M) ? 16u : 0u;
                uint32_t dst = sbase + (buf * BUFW + r * PITCH + c4 * 4) * 4;
                asm volatile("cp.async.cg.shared.global [%0], [%1], 16, %2;"
                             :: "r"(dst), "l"(gsrc), "r"(ss) : "memory");
            }
            {   // B (n = r)
                const unsigned* gsrc = Wt + (size_t)(col0 + r) * K + (ch * 8 + c4) * 4;
                uint32_t dst = sbase + (2 * BUFW + buf * BUFW + r * PITCH + c4 * 4) * 4;
                asm volatile("cp.async.cg.shared.global [%0], [%1], 16;"
                             :: "r"(dst), "l"(gsrc) : "memory");
            }
        }
        asm volatile("cp.async.commit_group;" ::: "memory");
    };

    float c[4][4][4];
#pragma unroll
    for (int i = 0; i < 4; i++)
#pragma unroll
        for (int j = 0; j < 4; j++)
#pragma unroll
            for (int q = 0; q < 4; q++) c[i][j][q] = 0.f;

    stage(0, 0);
    for (int ch = 0; ch < NCH; ch++) {
        int buf = ch & 1;
        if (ch + 1 < NCH) {
            stage(ch + 1, buf ^ 1);
            asm volatile("cp.async.wait_group 1;" ::: "memory");
        } else {
            asm volatile("cp.async.wait_group 0;" ::: "memory");
        }
        __syncthreads();

        const unsigned* As = smem_u + buf * BUFW;
        const unsigned* Bs = smem_u + 2 * BUFW + buf * BUFW;
#pragma unroll
        for (int kk = 0; kk < 32; kk += 8) {
            unsigned a[4][4], bb[4][2];
#pragma unroll
            for (int mt = 0; mt < 4; mt++) {
                int r = warp_m * 64 + mt * 16 + g;
                a[mt][0] = As[r * PITCH + kk + t];
                a[mt][1] = As[(r + 8) * PITCH + kk + t];
                a[mt][2] = As[r * PITCH + kk + t + 4];
                a[mt][3] = As[(r + 8) * PITCH + kk + t + 4];
            }
#pragma unroll
            for (int nt = 0; nt < 4; nt++) {
                int n = warp_n * 32 + nt * 8 + g;
                bb[nt][0] = Bs[n * PITCH + kk + t];
                bb[nt][1] = Bs[n * PITCH + kk + t + 4];
            }
#pragma unroll
            for (int mt = 0; mt < 4; mt++)
#pragma unroll
                for (int nt = 0; nt < 4; nt++)
                    asm volatile(
                        "mma.sync.aligned.m16n8k8.row.col.f32.tf32.tf32.f32 "
                        "{%0,%1,%2,%3}, {%4,%5,%6,%7}, {%8,%9}, {%0,%1,%2,%3};"
                        : "+f"(c[mt][nt][0]), "+f"(c[mt][nt][1]),
                          "+f"(c[mt][nt][2]), "+f"(c[mt][nt][3])
                        : "r"(a[mt][0]), "r"(a[mt][1]), "r"(a[mt][2]), "r"(a[mt][3]),
                          "r"(bb[nt][0]), "r"(bb[nt][1]));
        }
        __syncthreads();
    }

    // ---- epilogue: bias + sigmoid (optionally emit tf32 bits) ----
#pragma unroll
    for (int mt = 0; mt < 4; mt++) {
        int r0 = row0 + warp_m * 64 + mt * 16 + g;
#pragma unroll
        for (int nt = 0; nt < 4; nt++) {
            int col = col0 + warp_n * 32 + nt * 8 + 2 * t;
            float b0v = b[col], b1v = b[col + 1];
#pragma unroll
            for (int h = 0; h < 2; h++) {
                int row = r0 + 8 * h;
                if (row < M) {
                    float x = 1.0f / (1.0f + __expf(-(c[mt][nt][2 * h] + b0v)));
                    float y = 1.0f / (1.0f + __expf(-(c[mt][nt][2 * h + 1] + b1v)));
                    float2 o;
                    if (CVT) {
                        o.x = __uint_as_float(f2tf32(x));
                        o.y = __uint_as_float(f2tf32(y));
                    } else { o.x = x; o.y = y; }
                    *reinterpret_cast<float2*>(out + (size_t)row * HDIM + col) = o;
                }
            }
        }
    }
}

// ---------------- kernel 3: per-node partial dot products ----------------
__global__ void pspd_kernel(const float* __restrict__ wf, int Nn) {
    int gt = blockIdx.x * blockDim.x + threadIdx.x;
    int n = gt >> 5, lane = gt & 31;
    if (n >= Nn) return;
    const float4* row = reinterpret_cast<const float4*>(g_node2 + (size_t)n * HDIM);
    const float4* wfs = reinterpret_cast<const float4*>(wf);
    const float4* wfd = reinterpret_cast<const float4*>(wf + HDIM);
    float s = 0.f, d = 0.f;
#pragma unroll
    for (int k = lane; k < HDIM / 4; k += 32) {
        float4 v = row[k], a = wfs[k], bq = wfd[k];
        s += v.x * a.x + v.y * a.y + v.z * a.z + v.w * a.w;
        d += v.x * bq.x + v.y * bq.y + v.z * bq.z + v.w * bq.w;
    }
#pragma unroll
    for (int o = 16; o; o >>= 1) {
        s += __shfl_xor_sync(0xFFFFFFFFu, s, o);
        d += __shfl_xor_sync(0xFFFFFFFFu, d, o);
    }
    if (lane == 0) { g_ps[n] = s; g_pd[n] = d; }
}

// ---------------- kernel 4: edge embeddings + logits ----------------
__global__ void edge_kernel(const int* __restrict__ edge_index,
                            const float* __restrict__ bf,
                            float* __restrict__ out, int E) {
    int gt = blockIdx.x * blockDim.x + threadIdx.x;
    int e = gt >> 5, lane = gt & 31;
    if (e >= E) return;
    int s = clamp_idx(edge_index[e]);
    int d = clamp_idx(edge_index[E + e]);
    const float4* rs = reinterpret_cast<const float4*>(g_node2 + (size_t)s * HDIM);
    const float4* rd = reinterpret_cast<const float4*>(g_node2 + (size_t)d * HDIM);
    float4* o4 = reinterpret_cast<float4*>(out + (size_t)E + (size_t)e * (2 * HDIM));
    __stcs(o4 + lane,      rs[lane]);
    __stcs(o4 + 32 + lane, rs[32 + lane]);
    __stcs(o4 + 64 + lane, rd[lane]);
    __stcs(o4 + 96 + lane, rd[32 + lane]);
    if (lane == 0) __stcs(out + e, g_ps[s] + g_pd[d] + bf[0]);
}

// ---------------- launch ----------------
extern "C" void kernel_launch(void* const* d_in, const int* in_sizes, int n_in,
                              void* d_out, int out_size) {
    const float* edge_attr  = (const float*)d_in[0];
    const int*   edge_index = (const int*)d_in[1];
    const float* node_attr  = (const float*)d_in[2];
    const float* w0 = (const float*)d_in[3];
    const float* b0 = (const float*)d_in[4];
    const float* w1 = (const float*)d_in[5];
    const float* b1 = (const float*)d_in[6];
    const float* wf = (const float*)d_in[7];
    const float* bf = (const float*)d_in[8];
    float* out = (float*)d_out;

    const int E  = in_sizes[1] / 2;
    const int Nn = in_sizes[2] / FEDGE;

    float *mean_p, *node1_p, *node2_p;
    unsigned *a0_p, *w0t_p, *w1t_p;
    cudaGetSymbolAddress((void**)&mean_p,  g_mean);
    cudaGetSymbolAddress((void**)&node1_p, g_node1);
    cudaGetSymbolAddress((void**)&node2_p, g_node2);
    cudaGetSymbolAddress((void**)&a0_p,    g_a0);
    cudaGetSymbolAddress((void**)&w0t_p,   g_w0t);
    cudaGetSymbolAddress((void**)&w1t_p,   g_w1t);

    const int smem_bytes = 4 * BUFW * sizeof(unsigned);   // 73728
    cudaFuncSetAttribute((const void*)gemm_tc_kernel<256, true>,
                         cudaFuncAttributeMaxDynamicSharedMemorySize, smem_bytes);
    cudaFuncSetAttribute((const void*)gemm_tc_kernel<384, false>,
                         cudaFuncAttributeMaxDynamicSharedMemorySize, smem_bytes);

    {
        int total4 = (NNODES * FEDGE) / 4;
        zero_kernel<<<(total4 + 255) / 256, 256>>>();
    }
    {
        long long threads = (long long)E * 32;
        scatter_kernel<<<(int)((threads + 255) / 256), 256>>>(edge_attr, edge_index, E);
    }
    transpose_kernel<<<(256 * 256 + 255) / 256, 256>>>(w0, w0t_p, 256);
    transpose_kernel<<<(256 * 384 + 255) / 256, 256>>>(w1, w1t_p, 384);
    a0_convert_kernel<<<(Nn * 32 + 255) / 256, 256>>>(node_attr, Nn * 32);
    mean_fin_kernel<<<(NNODES * 32 + 255) / 256, 256>>>();

    dim3 grid((Nn + 127) / 128, 2);
    gemm_tc_kernel<256, true><<<grid, 256, smem_bytes>>>(
        a0_p, FEDGE, (const unsigned*)mean_p, w0t_p, b0, node1_p, Nn);
    gemm_tc_kernel<384, false><<<grid, 256, smem_bytes>>>(
        (const unsigned*)node1_p, HDIM, (const unsigned*)mean_p, w1t_p, b1, node2_p, Nn);
    {
        long long threads = (long long)Nn * 32;
        pspd_kernel<<<(int)((threads + 255) / 256), 256>>>(wf, Nn);
    }
    {
        long long threads = (long long)E * 32;
        edge_kernel<<<(int)((threads + 255) / 256), 256>>>(edge_index, bf, out, E);
    }
}